// round 15
// baseline (speedup 1.0000x reference)
#include <cuda_runtime.h>
#include <math.h>
#include <cstdint>

#define B_    256
#define Nn    21
#define PHs   12
#define FEAT  8
#define INP_  256
#define LAT_  64
#define HID_  512
#define OUTD  128
#define NT_   4
#define IN0_  328
#define XSTR  352
#define HZ_   320
#define G3_   1536
#define BN_   (B_*Nn)

#define OFF_DQ   0
#define OFF_COV  (B_*PHs*Nn*4)
#define OFF_XT   (OFF_COV + B_*PHs*Nn*6)

// self-inverse 16-block permutation
__host__ __device__ __forceinline__ int kperm(int k) {
    return (k & ~15) | ((k & 3) << 2) | ((k >> 2) & 3);
}

__device__ float g_xin[BN_*XSTR];
__device__ float g_hz[BN_*HZ_];
__device__ float g_base[BN_*G3_];
__device__ float g_hr[BN_*G3_];
__device__ float g_tmp0[BN_*HID_];
__device__ float g_h[2][BN_*HID_];
__device__ float g_hrnd[2][BN_*HID_];
__device__ float g_y[BN_*HID_];
__device__ float g_pqc[BN_*256];
__device__ float g_xc[BN_*FEAT];
__device__ float g_qc[BN_*4];
__device__ float g_G0n[Nn*Nn], g_Gn[Nn*Nn], g_Gqn[Nn*Nn], g_Gcn[Nn*Nn];
__device__ float g_W0r[NT_*HID_*XSTR];
__device__ float g_Wihr[NT_*G3_*HZ_];
__device__ float g_Whhr[NT_*G3_*HID_];
__device__ float g_Wqc[NT_*256*HID_];
__device__ float g_bqc[Nn*256];

__device__ __forceinline__ float tf32r(float x) {
    float r; asm("cvt.rna.tf32.f32 %0, %1;" : "=f"(r) : "f"(x)); return r;
}
__device__ __forceinline__ float tanha(float x) {
    float r; asm("tanh.approx.f32 %0, %1;" : "=f"(r) : "f"(x)); return r;
}
__device__ __forceinline__ float siga(float x) {
    return 0.5f + 0.5f * tanha(0.5f * x);
}
__device__ __forceinline__ uint32_t smem_u32(const void* p) {
    uint32_t a;
    asm("{ .reg .u64 t; cvta.to.shared.u64 t, %1; cvt.u32.u64 %0, t; }" : "=r"(a) : "l"(p));
    return a;
}
__device__ __forceinline__ void mma_tf32(float* d,
    uint32_t a0, uint32_t a1, uint32_t a2, uint32_t a3,
    uint32_t b0, uint32_t b1)
{
    asm volatile(
        "mma.sync.aligned.m16n8k8.row.col.f32.tf32.tf32.f32 "
        "{%0,%1,%2,%3}, {%4,%5,%6,%7}, {%8,%9}, {%0,%1,%2,%3};"
        : "+f"(d[0]), "+f"(d[1]), "+f"(d[2]), "+f"(d[3])
        : "r"(a0), "r"(a1), "r"(a2), "r"(a3), "r"(b0), "r"(b1));
}
__device__ __forceinline__ void cpa16(uint32_t dst, const float* src) {
    asm volatile("cp.async.cg.shared.global [%0], [%1], 16;"
                 :: "r"(dst), "l"(src) : "memory");
}
#define CP_COMMIT() asm volatile("cp.async.commit_group;" ::: "memory")
#define CP_WAIT0()  asm volatile("cp.async.wait_group 0;" ::: "memory")
#define CP_WAIT1()  asm volatile("cp.async.wait_group 1;" ::: "memory")

__global__ void knorms(const float* __restrict__ G0, const float* __restrict__ Grnn,
                       const float* __restrict__ GA, const float* __restrict__ Gq,
                       const float* __restrict__ Gc)
{
    int i = threadIdx.x;
    if (i >= 4*Nn) return;
    int mat = i / Nn, r = i % Nn;
    const float* src = (mat==0)?G0:(mat==1)?Grnn:(mat==2)?Gq:Gc;
    float* dst = (mat==0)?g_G0n:(mat==1)?g_Gn:(mat==2)?g_Gqn:g_Gcn;
    float s = 0.f;
    for (int m = 0; m < Nn; m++) s += fabsf(src[r*Nn+m]);
    s = fmaxf(s, 1e-12f);
    for (int m = 0; m < Nn; m++) {
        float v = src[r*Nn+m] / s;
        if (mat == 1) v += GA[r*Nn+m];
        dst[r*Nn+m] = v;
    }
}

__global__ void kprep(const float* __restrict__ x, const float* __restrict__ h,
                      const float* __restrict__ z, const float* __restrict__ qt,
                      float* __restrict__ out)
{
    int idx = blockIdx.x * blockDim.x + threadIdx.x;
    if (idx < BN_*XSTR) {
        int bn = idx / XSTR, j = idx % XSTR;
        int k = kperm(j);
        int b = bn / Nn, n = bn % Nn;
        float v = 0.f;
        if (k < FEAT)                 v = x[((b*2 + 0)*Nn + n)*FEAT + k];
        else if (k < FEAT+LAT_)       v = z[bn*LAT_ + (k - FEAT)];
        else if (k < IN0_)            v = h[bn*INP_ + (k - FEAT - LAT_)];
        g_xin[idx] = tf32r(v);
    }
    if (idx < BN_*HZ_) {
        int bn = idx / HZ_, j = idx % HZ_;
        int k = kperm(j);
        float v = (k < LAT_) ? z[bn*LAT_ + k] : h[bn*INP_ + (k - LAT_)];
        g_hz[idx] = tf32r(v);
    }
    if (idx < BN_*FEAT) {
        int bn = idx / FEAT, f = idx % FEAT;
        int b = bn / Nn, n = bn % Nn;
        float xv = x[((b*2 + 1)*Nn + n)*FEAT + f];
        g_xc[idx] = xv;
        out[OFF_XT + idx] = xv;
    }
    if (idx < BN_*4) g_qc[idx] = qt[idx];
}

#define NW0  (NT_*HID_*XSTR)
#define NWIH (NT_*G3_*HZ_)
#define NWHH (NT_*G3_*HID_)
__global__ void kroundw(const float* __restrict__ W0, const float* __restrict__ Wih,
                        const float* __restrict__ Whh)
{
    int idx = blockIdx.x * blockDim.x + threadIdx.x;
    if (idx < NW0) {
        int row = idx / XSTR, j = idx % XSTR;
        int k = kperm(j);
        g_W0r[idx] = (k < IN0_) ? tf32r(W0[(size_t)row*IN0_ + k]) : 0.f;
    } else if (idx < NW0 + NWIH) {
        int jj = idx - NW0;
        int row = jj / HZ_, j = jj % HZ_;
        int k = kperm(j);
        g_Wihr[jj] = tf32r(Wih[(size_t)row * IN0_ + FEAT + k]);
    } else if (idx < NW0 + NWIH + NWHH) {
        int jj = idx - NW0 - NWIH;
        int row = jj / HID_, j = jj % HID_;
        int k = kperm(j);
        g_Whhr[jj] = tf32r(Whh[(size_t)row*HID_ + k]);
    }
}

__global__ void kbuildwqc(const float* __restrict__ Wq, const float* __restrict__ Wc,
                          const float* __restrict__ bq, const float* __restrict__ bc)
{
    int idx = blockIdx.x * blockDim.x + threadIdx.x;
    if (idx < NT_*256*HID_) {
        int t = idx / (256*HID_);
        int r = (idx / HID_) % 256;
        int j = idx % HID_;
        int k = kperm(j);
        float v = (r < 128) ? Wq[((size_t)t*128 + r)*HID_ + k]
                            : Wc[((size_t)t*128 + (r-128))*HID_ + k];
        g_Wqc[idx] = tf32r(v);
    }
    if (idx < Nn*256) {
        int n = idx / 256, c = idx % 256;
        g_bqc[idx] = (c < 128) ? bq[n*128 + c] : bc[n*128 + (c-128)];
    }
}

// ---------------- mma.sync tf32 GEMM: CTA 128x256, 512 threads, warp 32x64, BK=32, 3-stage ----------------
#define SSTG  (128*32 + 256*32)
#define NSTG3 3

__global__ void __launch_bounds__(512, 1) ktc(
    int asel, int lda, int wsel, int ldw,
    int G, int K,
    const float* biasg, int csel,
    const int* __restrict__ T)
{
    extern __shared__ float smx[];

    const float* A = (asel==0)?g_xin : (asel==1)?g_hrnd[0] : (asel==2)?g_hrnd[1]
                   : (asel==3)?g_y : g_hz;
    const float* W = (wsel==0)?g_W0r : (wsel==1)?g_Wihr : (wsel==2)?g_Whhr : g_Wqc;
    const float* bias = biasg ? biasg : g_bqc;
    float* C = (csel==0)?g_tmp0 : (csel==1)?g_base : (csel==2)?g_hr : g_pqc;

    int n  = blockIdx.z;
    int t  = T[n];
    int b0 = blockIdx.x * 128;
    int g0 = blockIdx.y * 256;
    int tid  = threadIdx.x;
    int wid  = tid >> 5, lane = tid & 31;
    int wm = wid >> 2, wn = wid & 3;      // 4x4 warp grid; warp tile 32x64
    int gq = lane >> 2, tg = lane & 3;

    const size_t strideA = (size_t)Nn * lda;
    const float* An = A + ((size_t)b0 * Nn + n) * lda;
    const float* Wt = W + ((size_t)t * G + g0) * ldw;
    uint32_t smb = smem_u32(smx);

    float acc[2][8][4];
    #pragma unroll
    for (int a = 0; a < 2; a++)
        #pragma unroll
        for (int b = 0; b < 8; b++)
            #pragma unroll
            for (int c = 0; c < 4; c++) acc[a][b][c] = 0.f;

    int ntiles = K >> 5;

    // stage: A 128x32 (1024 chunks) + B 256x32 (2048 chunks); 6 cpa16/thread
    auto issue = [&](int kt, int buf) {
        int k0 = kt * 32;
        uint32_t sb = smb + buf * SSTG * 4;
        #pragma unroll
        for (int p = 0; p < 6; p++) {
            int id = p * 512 + tid;
            if (p < 2) {
                int row = id >> 3, c = id & 7;
                const float* src = An + (size_t)row * strideA + k0 + c*4;
                uint32_t dst = sb + (row*32 + ((c ^ ((row & 1) << 2)) << 2)) * 4;
                cpa16(dst, src);
            } else {
                int rid = id - 1024;
                int row = rid >> 3, c = rid & 7;
                const float* src = Wt + (size_t)row * ldw + k0 + c*4;
                uint32_t dst = sb + (4096 + row*32 + ((c ^ ((row & 1) << 2)) << 2)) * 4;
                cpa16(dst, src);
            }
        }
    };

    issue(0, 0); CP_COMMIT();
    issue(1, 1); CP_COMMIT();

    int ibuf = 2, cbuf = 0;
    for (int kt = 0; kt < ntiles; kt++) {
        if (kt + 1 < ntiles) CP_WAIT1(); else CP_WAIT0();
        __syncthreads();
        if (kt + 2 < ntiles) {
            issue(kt + 2, ibuf); CP_COMMIT();
            if (++ibuf == NSTG3) ibuf = 0;
        }

        const float* AsB = smx + cbuf * SSTG;
        const float* BsB = AsB + 4096;
        #pragma unroll
        for (int kh = 0; kh < 2; kh++) {
            float4 am[2], ah[2];
            #pragma unroll
            for (int mt = 0; mt < 2; mt++) {
                int row = wm*32 + mt*16 + gq;
                int ch = ((kh*4 + tg) ^ ((row & 1) << 2)) << 2;
                am[mt] = *(const float4*)(AsB + row*32 + ch);
                ah[mt] = *(const float4*)(AsB + (row + 8)*32 + ch);
            }
            #pragma unroll
            for (int nt = 0; nt < 8; nt++) {
                int col = wn*64 + nt*8 + gq;
                int ch = ((kh*4 + tg) ^ ((col & 1) << 2)) << 2;
                float4 bf = *(const float4*)(BsB + col*32 + ch);
                #pragma unroll
                for (int mt = 0; mt < 2; mt++) {
                    mma_tf32(acc[mt][nt],
                             __float_as_uint(am[mt].x), __float_as_uint(ah[mt].x),
                             __float_as_uint(am[mt].y), __float_as_uint(ah[mt].y),
                             __float_as_uint(bf.x), __float_as_uint(bf.y));
                    mma_tf32(acc[mt][nt],
                             __float_as_uint(am[mt].z), __float_as_uint(ah[mt].z),
                             __float_as_uint(am[mt].w), __float_as_uint(ah[mt].w),
                             __float_as_uint(bf.z), __float_as_uint(bf.w));
                }
            }
        }
        if (++cbuf == NSTG3) cbuf = 0;
    }

    const float* bp = bias + (size_t)n * G + g0;
    #pragma unroll
    for (int mt = 0; mt < 2; mt++) {
        int row = b0 + wm*32 + mt*16 + gq;
        float* C0 = C + ((size_t)row * Nn + n) * G + g0;
        float* C1 = C + ((size_t)(row + 8) * Nn + n) * G + g0;
        #pragma unroll
        for (int nt = 0; nt < 8; nt++) {
            int col = wn*64 + nt*8 + tg*2;
            float2 o0, o1;
            o0.x = acc[mt][nt][0] + bp[col];
            o0.y = acc[mt][nt][1] + bp[col + 1];
            o1.x = acc[mt][nt][2] + bp[col];
            o1.y = acc[mt][nt][3] + bp[col + 1];
            *(float2*)(C0 + col) = o0;
            *(float2*)(C1 + col) = o1;
        }
    }
}

__global__ void kmix_rnnh()
{
    int b = blockIdx.x, c0 = blockIdx.y * 64;
    __shared__ float sh[Nn][64];
    __shared__ float sG[Nn*Nn];
    int tid = threadIdx.x;
    for (int i = tid; i < Nn*Nn; i += 256) sG[i] = g_G0n[i];
    for (int i = tid; i < Nn*64; i += 256) {
        int m = i >> 6, c = i & 63;
        sh[m][c] = g_tmp0[((size_t)(b*Nn) + m) * HID_ + c0 + c];
    }
    __syncthreads();
    for (int i = tid; i < Nn*64; i += 256) {
        int n = i >> 6, c = i & 63;
        float s = 0.f;
        #pragma unroll
        for (int m = 0; m < Nn; m++) s += sG[n*Nn+m] * sh[m][c];
        size_t base = ((size_t)(b*Nn) + n) * HID_ + c0;
        g_h[0][base + c] = s;
        g_hrnd[0][base + kperm(c)] = tf32r(s);
    }
}

// ---------------- kgates v4: n-blocked mix loop ----------------
#define KG_SSUM 0
#define KG_SX2  (2*Nn*64)
#define KG_SHH2 (3*Nn*64)
#define KG_SG   (4*Nn*64)
#define KG_SXW  ((KG_SG + Nn*Nn + 3) & ~3)
#define KG_SXC  (KG_SXW + 4*3*64*8)
#define KG_TOT  (KG_SXC + Nn*8)

__global__ void __launch_bounds__(256, 3) kgates(
    const float* __restrict__ Wih, const int* __restrict__ T, int cur)
{
    extern __shared__ float sm[];
    __shared__ int sT[Nn];
    int b = blockIdx.x, c0 = blockIdx.y * 64;
    int tid = threadIdx.x;

    float* ssum = sm + KG_SSUM;
    float* sx2  = sm + KG_SX2;
    float* shh2 = sm + KG_SHH2;
    float* sG   = sm + KG_SG;
    float* sxw  = sm + KG_SXW;
    float* sxc  = sm + KG_SXC;

    if (tid < Nn) sT[tid] = T[tid];
    for (int i = tid; i < Nn*Nn; i += 256) sG[i] = g_Gn[i];
    for (int i = tid; i < Nn*8; i += 256) sxc[i] = g_xc[(size_t)b*Nn*FEAT + i];
    for (int i = tid; i < 4*3*64*2; i += 256) {
        int q4 = i & 1;
        int c  = (i >> 1) & 63;
        int s  = (i >> 7) % 3;
        int t  = i / (2*64*3);
        int g  = s*HID_ + c0 + c;
        float4 v = *(const float4*)(Wih + ((size_t)t * G3_ + g) * IN0_ + q4*4);
        *(float4*)(sxw + (((t*3 + s)*64 + c)*8) + q4*4) = v;
    }
    __syncthreads();

    for (int i = tid; i < 3*Nn*16; i += 256) {
        int s = i / (Nn*16);
        int rem = i % (Nn*16);
        int m = rem >> 4, q = rem & 15;
        int g = s*HID_ + c0 + q*4;
        size_t gi = ((size_t)(b*Nn) + m) * G3_ + g;
        float4 bs  = *(const float4*)(g_base + gi);
        float4 hr4 = *(const float4*)(g_hr + gi);
        const float* xc = sxc + m*8;
        int t = sT[m];
        const float* wxb = sxw + ((size_t)((t*3 + s)*64 + q*4))*8;
        float xr[4] = {bs.x, bs.y, bs.z, bs.w};
        #pragma unroll
        for (int j = 0; j < 4; j++) {
            const float* wr = wxb + j*8;
            #pragma unroll
            for (int k = 0; k < FEAT; k++) xr[j] += xc[k] * wr[k];
        }
        float hv[4] = {hr4.x, hr4.y, hr4.z, hr4.w};
        int off = m*64 + q*4;
        if (s < 2) {
            float* d = ssum + s*Nn*64 + off;
            #pragma unroll
            for (int j = 0; j < 4; j++) d[j] = xr[j] + hv[j];
        } else {
            #pragma unroll
            for (int j = 0; j < 4; j++) { sx2[off+j] = xr[j]; shh2[off+j] = hv[j]; }
        }
    }
    __syncthreads();

    {
        int c = tid & 63;
        int grp = tid >> 6;
        float a0[6], a1[6], a2[6], a3[6];
        #pragma unroll
        for (int j = 0; j < 6; j++) { a0[j]=0.f; a1[j]=0.f; a2[j]=0.f; a3[j]=0.f; }
        #pragma unroll
        for (int m = 0; m < Nn; m++) {
            float v0 = ssum[(0*Nn + m)*64 + c];
            float v1 = ssum[(1*Nn + m)*64 + c];
            float v2 = sx2[m*64 + c];
            float v3 = shh2[m*64 + c];
            #pragma unroll
            for (int j = 0; j < 6; j++) {
                int n = grp + 4*j;
                float gw = (n < Nn) ? sG[n*Nn + m] : 0.f;
                a0[j] += gw*v0; a1[j] += gw*v1; a2[j] += gw*v2; a3[j] += gw*v3;
            }
        }
        #pragma unroll
        for (int j = 0; j < 6; j++) {
            int n = grp + 4*j;
            if (n < Nn) {
                float r  = siga(a0[j]);
                float zg = siga(a1[j]);
                float nn = tanha(a2[j] + r*a3[j]);
                size_t base = ((size_t)(b*Nn) + n) * HID_ + c0;
                float hc = g_h[cur][base + c];
                float hnew = (1.f - zg)*nn + zg*hc;
                g_h[cur^1][base + c] = hnew;
                int cp = kperm(c);
                g_hrnd[cur^1][base + cp] = tf32r(hnew);
                g_y[base + cp] = tf32r(tanha(hnew));
            }
        }
    }
}

__global__ void __launch_bounds__(256) kheadmix(
    const float* __restrict__ W3, const float* __restrict__ b3,
    const float* __restrict__ W6, const float* __restrict__ b6,
    const int* __restrict__ T, float* __restrict__ out, int step)
{
    __shared__ float sq[Nn*OUTD];
    __shared__ float sc[Nn*OUTD];
    __shared__ float sy[Nn*OUTD];
    __shared__ float syc[Nn*OUTD];
    __shared__ float sGq[Nn*Nn], sGc[Nn*Nn];
    __shared__ int sT[Nn];

    int b = blockIdx.x;
    int tid = threadIdx.x;
    if (tid < Nn) sT[tid] = T[tid];
    for (int i = tid; i < Nn*Nn; i += 256) { sGq[i] = g_Gqn[i]; sGc[i] = g_Gcn[i]; }
    for (int i = tid; i < Nn*OUTD; i += 256) {
        int m = i >> 7, c = i & 127;
        sq[i] = g_pqc[((size_t)(b*Nn) + m) * 256 + c];
        sc[i] = g_pqc[((size_t)(b*Nn) + m) * 256 + 128 + c];
    }
    __syncthreads();
    for (int i = tid; i < Nn*OUTD; i += 256) {
        int n = i >> 7, c = i & 127;
        float s1 = 0.f, s2 = 0.f;
        #pragma unroll
        for (int m = 0; m < Nn; m++) {
            s1 += sGq[n*Nn+m] * sq[m*OUTD+c];
            s2 += sGc[n*Nn+m] * sc[m*OUTD+c];
        }
        sy[i]  = tanha(s1);
        syc[i] = tanha(s2);
    }
    __syncthreads();

    int wid = tid >> 5, lane = tid & 31;
    for (int n = wid; n < Nn; n += 8) {
        int t = sT[n];
        float val = 0.f;
        if (lane < 3) {
            const float* ys = sy + n*OUTD;
            const float* w  = W3 + ((size_t)t*3 + lane) * OUTD;
            #pragma unroll 8
            for (int k = 0; k < OUTD; k++) val += ys[k] * w[k];
            val += b3[n*3 + lane];
        } else if (lane < 9) {
            int a = lane - 3;
            const float* yc = syc + n*OUTD;
            const float* w  = W6 + ((size_t)t*6 + a) * OUTD;
            #pragma unroll 8
            for (int k = 0; k < OUTD; k++) val += yc[k] * w[k];
            val += b6[n*6 + a];
        }
        unsigned mask = 0xffffffffu;
        float v0 = __shfl_sync(mask, val, 0);
        float v1 = __shfl_sync(mask, val, 1);
        float v2 = __shfl_sync(mask, val, 2);
        float c0 = __shfl_sync(mask, val, 3);
        float c1 = __shfl_sync(mask, val, 4);
        float c2 = __shfl_sync(mask, val, 5);
        float c3 = __shfl_sync(mask, val, 6);
        float c4 = __shfl_sync(mask, val, 7);
        float c5 = __shfl_sync(mask, val, 8);
        if (lane == 0) {
            int bn = b*Nn + n;
            float theta = sqrtf(v0*v0 + v1*v1 + v2*v2);
            float w1 = cosf(0.5f * theta);
            float kk = (theta > 1e-8f) ? (sinf(0.5f*theta) / fmaxf(theta, 1e-8f)) : 0.5f;
            float dq0 = w1, dq1 = kk*v0, dq2 = kk*v1, dq3 = kk*v2;
            float* qc = g_qc + (size_t)bn * 4;
            float qw = qc[0], qx = qc[1], qy = qc[2], qz = qc[3];
            float nw = dq0*qw - (dq1*qx + dq2*qy + dq3*qz);
            float nx = dq0*qx + qw*dq1 + (dq2*qz - dq3*qy);
            float ny = dq0*qy + qw*dq2 + (dq3*qx - dq1*qz);
            float nz = dq0*qz + qw*dq3 + (dq1*qy - dq2*qx);
            qc[0]=nw; qc[1]=nx; qc[2]=ny; qc[3]=nz;
            float* xc = g_xc + (size_t)bn * FEAT;
            xc[0]=nw; xc[1]=nx; xc[2]=ny; xc[3]=nz;
            xc[4]=dq0; xc[5]=dq1; xc[6]=dq2; xc[7]=dq3;
            size_t od = ((size_t)b * PHs + step) * Nn + n;
            out[OFF_DQ  + od*4 + 0] = dq0; out[OFF_DQ + od*4 + 1] = dq1;
            out[OFF_DQ  + od*4 + 2] = dq2; out[OFF_DQ + od*4 + 3] = dq3;
            out[OFF_COV + od*6 + 0] = c0;  out[OFF_COV + od*6 + 1] = c1;
            out[OFF_COV + od*6 + 2] = c2;  out[OFF_COV + od*6 + 3] = c3;
            out[OFF_COV + od*6 + 4] = c4;  out[OFF_COV + od*6 + 5] = c5;
        }
    }
}

extern "C" void kernel_launch(void* const* d_in, const int* in_sizes, int n_in,
                              void* d_out, int out_size)
{
    const float* x    = (const float*)d_in[0];
    const float* h    = (const float*)d_in[1];
    const float* z    = (const float*)d_in[2];
    const float* q_t  = (const float*)d_in[3];
    const int*   T    = (const int*)  d_in[4];
    const float* W0   = (const float*)d_in[6];
    const float* b0p  = (const float*)d_in[7];
    const float* G0   = (const float*)d_in[8];
    const float* Wih  = (const float*)d_in[9];
    const float* Whh  = (const float*)d_in[10];
    const float* bih  = (const float*)d_in[11];
    const float* bhh  = (const float*)d_in[12];
    const float* Grnn = (const float*)d_in[13];
    const float* GA   = (const float*)d_in[14];
    const float* Wq   = (const float*)d_in[15];
    const float* bq   = (const float*)d_in[16];
    const float* Gq   = (const float*)d_in[17];
    const float* Wc   = (const float*)d_in[18];
    const float* bc   = (const float*)d_in[19];
    const float* Gc   = (const float*)d_in[20];
    const float* W3   = (const float*)d_in[21];
    const float* b3   = (const float*)d_in[22];
    const float* W6   = (const float*)d_in[23];
    const float* b6   = (const float*)d_in[24];
    float* out = (float*)d_out;

    const int SM_KTC = NSTG3 * SSTG * 4;
    const int SM_KG  = KG_TOT * 4;

    static cudaStream_t s_side = nullptr;
    static cudaEvent_t  s_ev1 = nullptr, s_ev2 = nullptr;
    static int attr_done = 0;
    if (!attr_done) {
        cudaFuncSetAttribute(ktc, cudaFuncAttributeMaxDynamicSharedMemorySize, SM_KTC);
        cudaFuncSetAttribute(kgates, cudaFuncAttributeMaxDynamicSharedMemorySize, SM_KG);
        cudaStreamCreateWithFlags(&s_side, cudaStreamNonBlocking);
        cudaEventCreateWithFlags(&s_ev1, cudaEventDisableTiming);
        cudaEventCreateWithFlags(&s_ev2, cudaEventDisableTiming);
        attr_done = 1;
    }
    cudaStream_t s0 = (cudaStream_t)0;

    knorms<<<1, 128>>>(G0, Grnn, GA, Gq, Gc);
    kprep<<<(BN_*XSTR + 255)/256, 256>>>(x, h, z, q_t, out);
    kroundw<<<(NW0 + NWIH + NWHH + 255)/256, 256>>>(W0, Wih, Whh);

    // launch #4 (ncu-captured): base = h_z(320) @ Wih_hz^T + bih
    ktc<<<dim3(2, G3_/256, Nn), 512, SM_KTC>>>(4, HZ_, 1, HZ_, G3_, HZ_, bih, 1, T);

    kbuildwqc<<<(NT_*256*HID_ + 255)/256, 256>>>(Wq, Wc, bq, bc);

    // tmp0 = xin(352 padded) @ W0^T + b0
    ktc<<<dim3(2, HID_/256, Nn), 512, SM_KTC>>>(0, XSTR, 0, XSTR, HID_, XSTR, b0p, 0, T);
    kmix_rnnh<<<dim3(B_, HID_/64), 256>>>();

    for (int t = 0; t < PHs; t++) {
        int cur = t & 1;
        ktc<<<dim3(2, G3_/256, Nn), 512, SM_KTC>>>(1 + cur, HID_, 2, HID_, G3_, HID_, bhh, 2, T);
        if (t > 0) cudaStreamWaitEvent(s0, s_ev2, 0);
        kgates<<<dim3(B_, HID_/64), 256, SM_KG>>>(Wih, T, cur);
        cudaEventRecord(s_ev1, s0);
        cudaStreamWaitEvent(s_side, s_ev1, 0);
        ktc<<<dim3(2, 1, Nn), 512, SM_KTC, s_side>>>(3, HID_, 3, HID_, 256, HID_, nullptr, 3, T);
        kheadmix<<<B_, 256, 0, s_side>>>(W3, b3, W6, b6, T, out, t);
        cudaEventRecord(s_ev2, s_side);
    }
    cudaStreamWaitEvent(s0, s_ev2, 0);
}

// round 16
// speedup vs baseline: 1.1933x; 1.1933x over previous
#include <cuda_runtime.h>
#include <math.h>
#include <cstdint>

#define B_    256
#define Nn    21
#define PHs   12
#define FEAT  8
#define INP_  256
#define LAT_  64
#define HID_  512
#define OUTD  128
#define NT_   4
#define IN0_  328
#define XSTR  352
#define HZ_   320
#define G3_   1536
#define BN_   (B_*Nn)

#define OFF_DQ   0
#define OFF_COV  (B_*PHs*Nn*4)
#define OFF_XT   (OFF_COV + B_*PHs*Nn*6)

// self-inverse 16-block permutation
__host__ __device__ __forceinline__ int kperm(int k) {
    return (k & ~15) | ((k & 3) << 2) | ((k >> 2) & 3);
}

__device__ float g_xin[BN_*XSTR];
__device__ float g_hz[BN_*HZ_];
__device__ float g_base[BN_*G3_];
__device__ float g_hr[BN_*G3_];
__device__ float g_tmp0[BN_*HID_];
__device__ float g_h[2][BN_*HID_];
__device__ float g_hrnd[2][BN_*HID_];
__device__ float g_y[BN_*HID_];
__device__ float g_pqc[BN_*256];
__device__ float g_xc[BN_*FEAT];
__device__ float g_qc[BN_*4];
__device__ float g_G0n[Nn*Nn], g_Gn[Nn*Nn], g_Gqn[Nn*Nn], g_Gcn[Nn*Nn];
__device__ float g_W0r[NT_*HID_*XSTR];
__device__ float g_Wihr[NT_*G3_*HZ_];
__device__ float g_Whhr[NT_*G3_*HID_];
__device__ float g_Wqc[NT_*256*HID_];
__device__ float g_bqc[Nn*256];

__device__ __forceinline__ float tf32r(float x) {
    float r; asm("cvt.rna.tf32.f32 %0, %1;" : "=f"(r) : "f"(x)); return r;
}
__device__ __forceinline__ float tanha(float x) {
    float r; asm("tanh.approx.f32 %0, %1;" : "=f"(r) : "f"(x)); return r;
}
__device__ __forceinline__ float siga(float x) {
    return 0.5f + 0.5f * tanha(0.5f * x);
}
__device__ __forceinline__ uint32_t smem_u32(const void* p) {
    uint32_t a;
    asm("{ .reg .u64 t; cvta.to.shared.u64 t, %1; cvt.u32.u64 %0, t; }" : "=r"(a) : "l"(p));
    return a;
}
__device__ __forceinline__ void mma_tf32(float* d,
    uint32_t a0, uint32_t a1, uint32_t a2, uint32_t a3,
    uint32_t b0, uint32_t b1)
{
    asm volatile(
        "mma.sync.aligned.m16n8k8.row.col.f32.tf32.tf32.f32 "
        "{%0,%1,%2,%3}, {%4,%5,%6,%7}, {%8,%9}, {%0,%1,%2,%3};"
        : "+f"(d[0]), "+f"(d[1]), "+f"(d[2]), "+f"(d[3])
        : "r"(a0), "r"(a1), "r"(a2), "r"(a3), "r"(b0), "r"(b1));
}
__device__ __forceinline__ void cpa16(uint32_t dst, const float* src) {
    asm volatile("cp.async.cg.shared.global [%0], [%1], 16;"
                 :: "r"(dst), "l"(src) : "memory");
}
#define CP_COMMIT() asm volatile("cp.async.commit_group;" ::: "memory")
#define CP_WAIT0()  asm volatile("cp.async.wait_group 0;" ::: "memory")
#define CP_WAIT1()  asm volatile("cp.async.wait_group 1;" ::: "memory")

__global__ void knorms(const float* __restrict__ G0, const float* __restrict__ Grnn,
                       const float* __restrict__ GA, const float* __restrict__ Gq,
                       const float* __restrict__ Gc)
{
    int i = threadIdx.x;
    if (i >= 4*Nn) return;
    int mat = i / Nn, r = i % Nn;
    const float* src = (mat==0)?G0:(mat==1)?Grnn:(mat==2)?Gq:Gc;
    float* dst = (mat==0)?g_G0n:(mat==1)?g_Gn:(mat==2)?g_Gqn:g_Gcn;
    float s = 0.f;
    for (int m = 0; m < Nn; m++) s += fabsf(src[r*Nn+m]);
    s = fmaxf(s, 1e-12f);
    for (int m = 0; m < Nn; m++) {
        float v = src[r*Nn+m] / s;
        if (mat == 1) v += GA[r*Nn+m];
        dst[r*Nn+m] = v;
    }
}

__global__ void kprep(const float* __restrict__ x, const float* __restrict__ h,
                      const float* __restrict__ z, const float* __restrict__ qt,
                      float* __restrict__ out)
{
    int idx = blockIdx.x * blockDim.x + threadIdx.x;
    if (idx < BN_*XSTR) {
        int bn = idx / XSTR, j = idx % XSTR;
        int k = kperm(j);
        int b = bn / Nn, n = bn % Nn;
        float v = 0.f;
        if (k < FEAT)                 v = x[((b*2 + 0)*Nn + n)*FEAT + k];
        else if (k < FEAT+LAT_)       v = z[bn*LAT_ + (k - FEAT)];
        else if (k < IN0_)            v = h[bn*INP_ + (k - FEAT - LAT_)];
        g_xin[idx] = tf32r(v);
    }
    if (idx < BN_*HZ_) {
        int bn = idx / HZ_, j = idx % HZ_;
        int k = kperm(j);
        float v = (k < LAT_) ? z[bn*LAT_ + k] : h[bn*INP_ + (k - LAT_)];
        g_hz[idx] = tf32r(v);
    }
    if (idx < BN_*FEAT) {
        int bn = idx / FEAT, f = idx % FEAT;
        int b = bn / Nn, n = bn % Nn;
        float xv = x[((b*2 + 1)*Nn + n)*FEAT + f];
        g_xc[idx] = xv;
        out[OFF_XT + idx] = xv;
    }
    if (idx < BN_*4) g_qc[idx] = qt[idx];
}

#define NW0  (NT_*HID_*XSTR)
#define NWIH (NT_*G3_*HZ_)
#define NWHH (NT_*G3_*HID_)
__global__ void kroundw(const float* __restrict__ W0, const float* __restrict__ Wih,
                        const float* __restrict__ Whh)
{
    int idx = blockIdx.x * blockDim.x + threadIdx.x;
    if (idx < NW0) {
        int row = idx / XSTR, j = idx % XSTR;
        int k = kperm(j);
        g_W0r[idx] = (k < IN0_) ? tf32r(W0[(size_t)row*IN0_ + k]) : 0.f;
    } else if (idx < NW0 + NWIH) {
        int jj = idx - NW0;
        int row = jj / HZ_, j = jj % HZ_;
        int k = kperm(j);
        g_Wihr[jj] = tf32r(Wih[(size_t)row * IN0_ + FEAT + k]);
    } else if (idx < NW0 + NWIH + NWHH) {
        int jj = idx - NW0 - NWIH;
        int row = jj / HID_, j = jj % HID_;
        int k = kperm(j);
        g_Whhr[jj] = tf32r(Whh[(size_t)row*HID_ + k]);
    }
}

__global__ void kbuildwqc(const float* __restrict__ Wq, const float* __restrict__ Wc,
                          const float* __restrict__ bq, const float* __restrict__ bc)
{
    int idx = blockIdx.x * blockDim.x + threadIdx.x;
    if (idx < NT_*256*HID_) {
        int t = idx / (256*HID_);
        int r = (idx / HID_) % 256;
        int j = idx % HID_;
        int k = kperm(j);
        float v = (r < 128) ? Wq[((size_t)t*128 + r)*HID_ + k]
                            : Wc[((size_t)t*128 + (r-128))*HID_ + k];
        g_Wqc[idx] = tf32r(v);
    }
    if (idx < Nn*256) {
        int n = idx / 256, c = idx % 256;
        g_bqc[idx] = (c < 128) ? bq[n*128 + c] : bc[n*128 + (c-128)];
    }
}

// ---------------- mma.sync tf32 GEMM: CTA 128x256, 256 thr, warp 64x64, BK=32, 3-stage ----------------
// g0 = (ybase + blockIdx.y*ystep)*256  -> allows even/odd N-block split launches
#define SSTG  (128*32 + 256*32)
#define NSTG3 3

__global__ void __launch_bounds__(256, 1) ktc(
    int asel, int lda, int wsel, int ldw,
    int G, int K,
    const float* biasg, int csel,
    const int* __restrict__ T, int ybase, int ystep)
{
    extern __shared__ float smx[];

    const float* A = (asel==0)?g_xin : (asel==1)?g_hrnd[0] : (asel==2)?g_hrnd[1]
                   : (asel==3)?g_y : g_hz;
    const float* W = (wsel==0)?g_W0r : (wsel==1)?g_Wihr : (wsel==2)?g_Whhr : g_Wqc;
    const float* bias = biasg ? biasg : g_bqc;
    float* C = (csel==0)?g_tmp0 : (csel==1)?g_base : (csel==2)?g_hr : g_pqc;

    int n  = blockIdx.z;
    int t  = T[n];
    int b0 = blockIdx.x * 128;
    int g0 = (ybase + blockIdx.y * ystep) * 256;
    int tid  = threadIdx.x;
    int wid  = tid >> 5, lane = tid & 31;
    int wm = wid >> 2, wn = wid & 3;
    int gq = lane >> 2, tg = lane & 3;

    const size_t strideA = (size_t)Nn * lda;
    const float* An = A + ((size_t)b0 * Nn + n) * lda;
    const float* Wt = W + ((size_t)t * G + g0) * ldw;
    uint32_t smb = smem_u32(smx);

    float acc[4][8][4];
    #pragma unroll
    for (int a = 0; a < 4; a++)
        #pragma unroll
        for (int b = 0; b < 8; b++)
            #pragma unroll
            for (int c = 0; c < 4; c++) acc[a][b][c] = 0.f;

    int ntiles = K >> 5;

    auto issue = [&](int kt, int buf) {
        int k0 = kt * 32;
        uint32_t sb = smb + buf * SSTG * 4;
        #pragma unroll
        for (int p = 0; p < 12; p++) {
            int id = p * 256 + tid;
            if (p < 4) {
                int row = id >> 3, c = id & 7;
                const float* src = An + (size_t)row * strideA + k0 + c*4;
                uint32_t dst = sb + (row*32 + ((c ^ ((row & 1) << 2)) << 2)) * 4;
                cpa16(dst, src);
            } else {
                int rid = id - 1024;
                int row = rid >> 3, c = rid & 7;
                const float* src = Wt + (size_t)row * ldw + k0 + c*4;
                uint32_t dst = sb + (4096 + row*32 + ((c ^ ((row & 1) << 2)) << 2)) * 4;
                cpa16(dst, src);
            }
        }
    };

    issue(0, 0); CP_COMMIT();
    issue(1, 1); CP_COMMIT();

    int ibuf = 2, cbuf = 0;
    for (int kt = 0; kt < ntiles; kt++) {
        if (kt + 1 < ntiles) CP_WAIT1(); else CP_WAIT0();
        __syncthreads();
        if (kt + 2 < ntiles) {
            issue(kt + 2, ibuf); CP_COMMIT();
            if (++ibuf == NSTG3) ibuf = 0;
        }

        const float* AsB = smx + cbuf * SSTG;
        const float* BsB = AsB + 4096;
        #pragma unroll
        for (int kh = 0; kh < 2; kh++) {
            float4 am[4], ah[4];
            #pragma unroll
            for (int mt = 0; mt < 4; mt++) {
                int row = wm*64 + mt*16 + gq;
                int ch = ((kh*4 + tg) ^ ((row & 1) << 2)) << 2;
                am[mt] = *(const float4*)(AsB + row*32 + ch);
                ah[mt] = *(const float4*)(AsB + (row + 8)*32 + ch);
            }
            #pragma unroll
            for (int nt = 0; nt < 8; nt++) {
                int col = wn*64 + nt*8 + gq;
                int ch = ((kh*4 + tg) ^ ((col & 1) << 2)) << 2;
                float4 bf = *(const float4*)(BsB + col*32 + ch);
                #pragma unroll
                for (int mt = 0; mt < 4; mt++) {
                    mma_tf32(acc[mt][nt],
                             __float_as_uint(am[mt].x), __float_as_uint(ah[mt].x),
                             __float_as_uint(am[mt].y), __float_as_uint(ah[mt].y),
                             __float_as_uint(bf.x), __float_as_uint(bf.y));
                    mma_tf32(acc[mt][nt],
                             __float_as_uint(am[mt].z), __float_as_uint(ah[mt].z),
                             __float_as_uint(am[mt].w), __float_as_uint(ah[mt].w),
                             __float_as_uint(bf.z), __float_as_uint(bf.w));
                }
            }
        }
        if (++cbuf == NSTG3) cbuf = 0;
    }

    const float* bp = bias + (size_t)n * G + g0;
    #pragma unroll
    for (int mt = 0; mt < 4; mt++) {
        int row = b0 + wm*64 + mt*16 + gq;
        float* C0 = C + ((size_t)row * Nn + n) * G + g0;
        float* C1 = C + ((size_t)(row + 8) * Nn + n) * G + g0;
        #pragma unroll
        for (int nt = 0; nt < 8; nt++) {
            int col = wn*64 + nt*8 + tg*2;
            float2 o0, o1;
            o0.x = acc[mt][nt][0] + bp[col];
            o0.y = acc[mt][nt][1] + bp[col + 1];
            o1.x = acc[mt][nt][2] + bp[col];
            o1.y = acc[mt][nt][3] + bp[col + 1];
            *(float2*)(C0 + col) = o0;
            *(float2*)(C1 + col) = o1;
        }
    }
}

__global__ void kmix_rnnh()
{
    int b = blockIdx.x, c0 = blockIdx.y * 64;
    __shared__ float sh[Nn][64];
    __shared__ float sG[Nn*Nn];
    int tid = threadIdx.x;
    for (int i = tid; i < Nn*Nn; i += 256) sG[i] = g_G0n[i];
    for (int i = tid; i < Nn*64; i += 256) {
        int m = i >> 6, c = i & 63;
        sh[m][c] = g_tmp0[((size_t)(b*Nn) + m) * HID_ + c0 + c];
    }
    __syncthreads();
    for (int i = tid; i < Nn*64; i += 256) {
        int n = i >> 6, c = i & 63;
        float s = 0.f;
        #pragma unroll
        for (int m = 0; m < Nn; m++) s += sG[n*Nn+m] * sh[m][c];
        size_t base = ((size_t)(b*Nn) + n) * HID_ + c0;
        g_h[0][base + c] = s;
        g_hrnd[0][base + kperm(c)] = tf32r(s);
    }
}

// ---------------- kgates v4 (n-blocked mix), channel-half split ----------------
#define KG_SSUM 0
#define KG_SX2  (2*Nn*64)
#define KG_SHH2 (3*Nn*64)
#define KG_SG   (4*Nn*64)
#define KG_SXW  ((KG_SG + Nn*Nn + 3) & ~3)
#define KG_SXC  (KG_SXW + 4*3*64*8)
#define KG_TOT  (KG_SXC + Nn*8)

__global__ void __launch_bounds__(256, 3) kgates(
    const float* __restrict__ Wih, const int* __restrict__ T, int cur, int c0base)
{
    extern __shared__ float sm[];
    __shared__ int sT[Nn];
    int b = blockIdx.x, c0 = c0base + blockIdx.y * 64;
    int tid = threadIdx.x;

    float* ssum = sm + KG_SSUM;
    float* sx2  = sm + KG_SX2;
    float* shh2 = sm + KG_SHH2;
    float* sG   = sm + KG_SG;
    float* sxw  = sm + KG_SXW;
    float* sxc  = sm + KG_SXC;

    if (tid < Nn) sT[tid] = T[tid];
    for (int i = tid; i < Nn*Nn; i += 256) sG[i] = g_Gn[i];
    for (int i = tid; i < Nn*8; i += 256) sxc[i] = g_xc[(size_t)b*Nn*FEAT + i];
    for (int i = tid; i < 4*3*64*2; i += 256) {
        int q4 = i & 1;
        int c  = (i >> 1) & 63;
        int s  = (i >> 7) % 3;
        int t  = i / (2*64*3);
        int g  = s*HID_ + c0 + c;
        float4 v = *(const float4*)(Wih + ((size_t)t * G3_ + g) * IN0_ + q4*4);
        *(float4*)(sxw + (((t*3 + s)*64 + c)*8) + q4*4) = v;
    }
    __syncthreads();

    for (int i = tid; i < 3*Nn*16; i += 256) {
        int s = i / (Nn*16);
        int rem = i % (Nn*16);
        int m = rem >> 4, q = rem & 15;
        int g = s*HID_ + c0 + q*4;
        size_t gi = ((size_t)(b*Nn) + m) * G3_ + g;
        float4 bs  = *(const float4*)(g_base + gi);
        float4 hr4 = *(const float4*)(g_hr + gi);
        const float* xc = sxc + m*8;
        int t = sT[m];
        const float* wxb = sxw + ((size_t)((t*3 + s)*64 + q*4))*8;
        float xr[4] = {bs.x, bs.y, bs.z, bs.w};
        #pragma unroll
        for (int j = 0; j < 4; j++) {
            const float* wr = wxb + j*8;
            #pragma unroll
            for (int k = 0; k < FEAT; k++) xr[j] += xc[k] * wr[k];
        }
        float hv[4] = {hr4.x, hr4.y, hr4.z, hr4.w};
        int off = m*64 + q*4;
        if (s < 2) {
            float* d = ssum + s*Nn*64 + off;
            #pragma unroll
            for (int j = 0; j < 4; j++) d[j] = xr[j] + hv[j];
        } else {
            #pragma unroll
            for (int j = 0; j < 4; j++) { sx2[off+j] = xr[j]; shh2[off+j] = hv[j]; }
        }
    }
    __syncthreads();

    {
        int c = tid & 63;
        int grp = tid >> 6;
        float a0[6], a1[6], a2[6], a3[6];
        #pragma unroll
        for (int j = 0; j < 6; j++) { a0[j]=0.f; a1[j]=0.f; a2[j]=0.f; a3[j]=0.f; }
        #pragma unroll
        for (int m = 0; m < Nn; m++) {
            float v0 = ssum[(0*Nn + m)*64 + c];
            float v1 = ssum[(1*Nn + m)*64 + c];
            float v2 = sx2[m*64 + c];
            float v3 = shh2[m*64 + c];
            #pragma unroll
            for (int j = 0; j < 6; j++) {
                int n = grp + 4*j;
                float gw = (n < Nn) ? sG[n*Nn + m] : 0.f;
                a0[j] += gw*v0; a1[j] += gw*v1; a2[j] += gw*v2; a3[j] += gw*v3;
            }
        }
        #pragma unroll
        for (int j = 0; j < 6; j++) {
            int n = grp + 4*j;
            if (n < Nn) {
                float r  = siga(a0[j]);
                float zg = siga(a1[j]);
                float nn = tanha(a2[j] + r*a3[j]);
                size_t base = ((size_t)(b*Nn) + n) * HID_ + c0;
                float hc = g_h[cur][base + c];
                float hnew = (1.f - zg)*nn + zg*hc;
                g_h[cur^1][base + c] = hnew;
                int cp = kperm(c);
                g_hrnd[cur^1][base + cp] = tf32r(hnew);
                g_y[base + cp] = tf32r(tanha(hnew));
            }
        }
    }
}

__global__ void __launch_bounds__(256) kheadmix(
    const float* __restrict__ W3, const float* __restrict__ b3,
    const float* __restrict__ W6, const float* __restrict__ b6,
    const int* __restrict__ T, float* __restrict__ out, int step)
{
    __shared__ float sq[Nn*OUTD];
    __shared__ float sc[Nn*OUTD];
    __shared__ float sy[Nn*OUTD];
    __shared__ float syc[Nn*OUTD];
    __shared__ float sGq[Nn*Nn], sGc[Nn*Nn];
    __shared__ int sT[Nn];

    int b = blockIdx.x;
    int tid = threadIdx.x;
    if (tid < Nn) sT[tid] = T[tid];
    for (int i = tid; i < Nn*Nn; i += 256) { sGq[i] = g_Gqn[i]; sGc[i] = g_Gcn[i]; }
    for (int i = tid; i < Nn*OUTD; i += 256) {
        int m = i >> 7, c = i & 127;
        sq[i] = g_pqc[((size_t)(b*Nn) + m) * 256 + c];
        sc[i] = g_pqc[((size_t)(b*Nn) + m) * 256 + 128 + c];
    }
    __syncthreads();
    for (int i = tid; i < Nn*OUTD; i += 256) {
        int n = i >> 7, c = i & 127;
        float s1 = 0.f, s2 = 0.f;
        #pragma unroll
        for (int m = 0; m < Nn; m++) {
            s1 += sGq[n*Nn+m] * sq[m*OUTD+c];
            s2 += sGc[n*Nn+m] * sc[m*OUTD+c];
        }
        sy[i]  = tanha(s1);
        syc[i] = tanha(s2);
    }
    __syncthreads();

    int wid = tid >> 5, lane = tid & 31;
    for (int n = wid; n < Nn; n += 8) {
        int t = sT[n];
        float val = 0.f;
        if (lane < 3) {
            const float* ys = sy + n*OUTD;
            const float* w  = W3 + ((size_t)t*3 + lane) * OUTD;
            #pragma unroll 8
            for (int k = 0; k < OUTD; k++) val += ys[k] * w[k];
            val += b3[n*3 + lane];
        } else if (lane < 9) {
            int a = lane - 3;
            const float* yc = syc + n*OUTD;
            const float* w  = W6 + ((size_t)t*6 + a) * OUTD;
            #pragma unroll 8
            for (int k = 0; k < OUTD; k++) val += yc[k] * w[k];
            val += b6[n*6 + a];
        }
        unsigned mask = 0xffffffffu;
        float v0 = __shfl_sync(mask, val, 0);
        float v1 = __shfl_sync(mask, val, 1);
        float v2 = __shfl_sync(mask, val, 2);
        float c0 = __shfl_sync(mask, val, 3);
        float c1 = __shfl_sync(mask, val, 4);
        float c2 = __shfl_sync(mask, val, 5);
        float c3 = __shfl_sync(mask, val, 6);
        float c4 = __shfl_sync(mask, val, 7);
        float c5 = __shfl_sync(mask, val, 8);
        if (lane == 0) {
            int bn = b*Nn + n;
            float theta = sqrtf(v0*v0 + v1*v1 + v2*v2);
            float w1 = cosf(0.5f * theta);
            float kk = (theta > 1e-8f) ? (sinf(0.5f*theta) / fmaxf(theta, 1e-8f)) : 0.5f;
            float dq0 = w1, dq1 = kk*v0, dq2 = kk*v1, dq3 = kk*v2;
            float* qc = g_qc + (size_t)bn * 4;
            float qw = qc[0], qx = qc[1], qy = qc[2], qz = qc[3];
            float nw = dq0*qw - (dq1*qx + dq2*qy + dq3*qz);
            float nx = dq0*qx + qw*dq1 + (dq2*qz - dq3*qy);
            float ny = dq0*qy + qw*dq2 + (dq3*qx - dq1*qz);
            float nz = dq0*qz + qw*dq3 + (dq1*qy - dq2*qx);
            qc[0]=nw; qc[1]=nx; qc[2]=ny; qc[3]=nz;
            float* xc = g_xc + (size_t)bn * FEAT;
            xc[0]=nw; xc[1]=nx; xc[2]=ny; xc[3]=nz;
            xc[4]=dq0; xc[5]=dq1; xc[6]=dq2; xc[7]=dq3;
            size_t od = ((size_t)b * PHs + step) * Nn + n;
            out[OFF_DQ  + od*4 + 0] = dq0; out[OFF_DQ + od*4 + 1] = dq1;
            out[OFF_DQ  + od*4 + 2] = dq2; out[OFF_DQ + od*4 + 3] = dq3;
            out[OFF_COV + od*6 + 0] = c0;  out[OFF_COV + od*6 + 1] = c1;
            out[OFF_COV + od*6 + 2] = c2;  out[OFF_COV + od*6 + 3] = c3;
            out[OFF_COV + od*6 + 4] = c4;  out[OFF_COV + od*6 + 5] = c5;
        }
    }
}

extern "C" void kernel_launch(void* const* d_in, const int* in_sizes, int n_in,
                              void* d_out, int out_size)
{
    const float* x    = (const float*)d_in[0];
    const float* h    = (const float*)d_in[1];
    const float* z    = (const float*)d_in[2];
    const float* q_t  = (const float*)d_in[3];
    const int*   T    = (const int*)  d_in[4];
    const float* W0   = (const float*)d_in[6];
    const float* b0p  = (const float*)d_in[7];
    const float* G0   = (const float*)d_in[8];
    const float* Wih  = (const float*)d_in[9];
    const float* Whh  = (const float*)d_in[10];
    const float* bih  = (const float*)d_in[11];
    const float* bhh  = (const float*)d_in[12];
    const float* Grnn = (const float*)d_in[13];
    const float* GA   = (const float*)d_in[14];
    const float* Wq   = (const float*)d_in[15];
    const float* bq   = (const float*)d_in[16];
    const float* Gq   = (const float*)d_in[17];
    const float* Wc   = (const float*)d_in[18];
    const float* bc   = (const float*)d_in[19];
    const float* Gc   = (const float*)d_in[20];
    const float* W3   = (const float*)d_in[21];
    const float* b3   = (const float*)d_in[22];
    const float* W6   = (const float*)d_in[23];
    const float* b6   = (const float*)d_in[24];
    float* out = (float*)d_out;

    const int SM_KTC = NSTG3 * SSTG * 4;
    const int SM_KG  = KG_TOT * 4;

    static cudaStream_t s_side = nullptr;
    static cudaEvent_t  s_evA = nullptr, s_e1a = nullptr, s_e1b = nullptr, s_evS = nullptr;
    static int attr_done = 0;
    if (!attr_done) {
        cudaFuncSetAttribute(ktc, cudaFuncAttributeMaxDynamicSharedMemorySize, SM_KTC);
        cudaFuncSetAttribute(kgates, cudaFuncAttributeMaxDynamicSharedMemorySize, SM_KG);
        cudaStreamCreateWithFlags(&s_side, cudaStreamNonBlocking);
        cudaEventCreateWithFlags(&s_evA, cudaEventDisableTiming);
        cudaEventCreateWithFlags(&s_e1a, cudaEventDisableTiming);
        cudaEventCreateWithFlags(&s_e1b, cudaEventDisableTiming);
        cudaEventCreateWithFlags(&s_evS, cudaEventDisableTiming);
        attr_done = 1;
    }
    cudaStream_t s0 = (cudaStream_t)0;

    knorms<<<1, 128>>>(G0, Grnn, GA, Gq, Gc);
    kprep<<<(BN_*XSTR + 255)/256, 256>>>(x, h, z, q_t, out);
    kroundw<<<(NW0 + NWIH + NWHH + 255)/256, 256>>>(W0, Wih, Whh);

    // launch #4 (ncu-captured): base = h_z(320) @ Wih_hz^T + bih
    ktc<<<dim3(2, 6, Nn), 256, SM_KTC>>>(4, HZ_, 1, HZ_, G3_, HZ_, bih, 1, T, 0, 1);

    kbuildwqc<<<(NT_*256*HID_ + 255)/256, 256>>>(Wq, Wc, bq, bc);

    // tmp0 = xin(352 padded) @ W0^T + b0
    ktc<<<dim3(2, 2, Nn), 256, SM_KTC>>>(0, XSTR, 0, XSTR, HID_, XSTR, b0p, 0, T, 0, 1);
    kmix_rnnh<<<dim3(B_, HID_/64), 256>>>();

    for (int t = 0; t < PHs; t++) {
        int cur = t & 1;
        // hrA: even N-blocks {0,2,4} (g slices needed by kgatesA: c0<256)
        if (t > 0) cudaStreamWaitEvent(s0, s_e1a, 0);   // kgatesA(t-1) wrote g_hrnd/g_h
        ktc<<<dim3(2, 3, Nn), 256, SM_KTC, s0>>>(1 + cur, HID_, 2, HID_, G3_, HID_, bhh, 2, T, 0, 2);
        cudaEventRecord(s_evA, s0);
        // hrB: odd N-blocks {1,3,5}
        ktc<<<dim3(2, 3, Nn), 256, SM_KTC, s0>>>(1 + cur, HID_, 2, HID_, G3_, HID_, bhh, 2, T, 1, 2);
        // kgatesB (c0 >= 256): needs kheadmix(t-1) (g_xc) + pqc(t-1) (g_y read done)
        if (t > 0) cudaStreamWaitEvent(s0, s_evS, 0);
        kgates<<<dim3(B_, 4), 256, SM_KG, s0>>>(Wih, T, cur, 256);
        cudaEventRecord(s_e1b, s0);
        // kgatesA (c0 < 256) on side stream, overlapping hrB/kgatesB
        cudaStreamWaitEvent(s_side, s_evA, 0);
        kgates<<<dim3(B_, 4), 256, SM_KG, s_side>>>(Wih, T, cur, 0);
        cudaEventRecord(s_e1a, s_side);
        // output head: needs full g_y (kgatesA in-stream, kgatesB via e1b)
        cudaStreamWaitEvent(s_side, s_e1b, 0);
        ktc<<<dim3(2, 1, Nn), 256, SM_KTC, s_side>>>(3, HID_, 3, HID_, 256, HID_, nullptr, 3, T, 0, 1);
        kheadmix<<<B_, 256, 0, s_side>>>(W3, b3, W6, b6, T, out, t);
        cudaEventRecord(s_evS, s_side);
    }
    cudaStreamWaitEvent(s0, s_evS, 0);
}

// round 17
// speedup vs baseline: 1.1939x; 1.0005x over previous
#include <cuda_runtime.h>
#include <math.h>
#include <cstdint>

#define B_    256
#define Nn    21
#define PHs   12
#define FEAT  8
#define INP_  256
#define LAT_  64
#define HID_  512
#define OUTD  128
#define NT_   4
#define IN0_  328
#define XSTR  352
#define HZ_   320
#define G3_   1536
#define BN_   (B_*Nn)

#define OFF_DQ   0
#define OFF_COV  (B_*PHs*Nn*4)
#define OFF_XT   (OFF_COV + B_*PHs*Nn*6)

// self-inverse 16-block permutation
__host__ __device__ __forceinline__ int kperm(int k) {
    return (k & ~15) | ((k & 3) << 2) | ((k >> 2) & 3);
}

__device__ float g_xin[BN_*XSTR];
__device__ float g_hz[BN_*HZ_];
__device__ float g_base[BN_*G3_];
__device__ float g_hr[BN_*G3_];
__device__ float g_tmp0[BN_*HID_];
__device__ float g_h[2][BN_*HID_];
__device__ float g_hrnd[2][BN_*HID_];
__device__ float g_y[BN_*HID_];
__device__ float g_pqc[BN_*256];
__device__ float g_xc[BN_*FEAT];
__device__ float g_qc[BN_*4];
__device__ float g_G0n[Nn*Nn], g_Gn[Nn*Nn], g_Gqn[Nn*Nn], g_Gcn[Nn*Nn];
__device__ float g_W0r[NT_*HID_*XSTR];
__device__ float g_Wihr[NT_*G3_*HZ_];
__device__ float g_Whhr[NT_*G3_*HID_];
__device__ float g_Wqc[NT_*256*HID_];
__device__ float g_bqc[Nn*256];

__device__ __forceinline__ float tf32r(float x) {
    float r; asm("cvt.rna.tf32.f32 %0, %1;" : "=f"(r) : "f"(x)); return r;
}
__device__ __forceinline__ float tanha(float x) {
    float r; asm("tanh.approx.f32 %0, %1;" : "=f"(r) : "f"(x)); return r;
}
__device__ __forceinline__ float siga(float x) {
    return 0.5f + 0.5f * tanha(0.5f * x);
}
__device__ __forceinline__ uint32_t smem_u32(const void* p) {
    uint32_t a;
    asm("{ .reg .u64 t; cvta.to.shared.u64 t, %1; cvt.u32.u64 %0, t; }" : "=r"(a) : "l"(p));
    return a;
}
__device__ __forceinline__ void mma_tf32(float* d,
    uint32_t a0, uint32_t a1, uint32_t a2, uint32_t a3,
    uint32_t b0, uint32_t b1)
{
    asm volatile(
        "mma.sync.aligned.m16n8k8.row.col.f32.tf32.tf32.f32 "
        "{%0,%1,%2,%3}, {%4,%5,%6,%7}, {%8,%9}, {%0,%1,%2,%3};"
        : "+f"(d[0]), "+f"(d[1]), "+f"(d[2]), "+f"(d[3])
        : "r"(a0), "r"(a1), "r"(a2), "r"(a3), "r"(b0), "r"(b1));
}
__device__ __forceinline__ void cpa16(uint32_t dst, const float* src) {
    asm volatile("cp.async.cg.shared.global [%0], [%1], 16;"
                 :: "r"(dst), "l"(src) : "memory");
}
#define CP_COMMIT() asm volatile("cp.async.commit_group;" ::: "memory")
#define CP_WAIT0()  asm volatile("cp.async.wait_group 0;" ::: "memory")
#define CP_WAIT1()  asm volatile("cp.async.wait_group 1;" ::: "memory")

__global__ void knorms(const float* __restrict__ G0, const float* __restrict__ Grnn,
                       const float* __restrict__ GA, const float* __restrict__ Gq,
                       const float* __restrict__ Gc)
{
    int i = threadIdx.x;
    if (i >= 4*Nn) return;
    int mat = i / Nn, r = i % Nn;
    const float* src = (mat==0)?G0:(mat==1)?Grnn:(mat==2)?Gq:Gc;
    float* dst = (mat==0)?g_G0n:(mat==1)?g_Gn:(mat==2)?g_Gqn:g_Gcn;
    float s = 0.f;
    for (int m = 0; m < Nn; m++) s += fabsf(src[r*Nn+m]);
    s = fmaxf(s, 1e-12f);
    for (int m = 0; m < Nn; m++) {
        float v = src[r*Nn+m] / s;
        if (mat == 1) v += GA[r*Nn+m];
        dst[r*Nn+m] = v;
    }
}

__global__ void kprep(const float* __restrict__ x, const float* __restrict__ h,
                      const float* __restrict__ z, const float* __restrict__ qt,
                      float* __restrict__ out)
{
    int idx = blockIdx.x * blockDim.x + threadIdx.x;
    if (idx < BN_*XSTR) {
        int bn = idx / XSTR, j = idx % XSTR;
        int k = kperm(j);
        int b = bn / Nn, n = bn % Nn;
        float v = 0.f;
        if (k < FEAT)                 v = x[((b*2 + 0)*Nn + n)*FEAT + k];
        else if (k < FEAT+LAT_)       v = z[bn*LAT_ + (k - FEAT)];
        else if (k < IN0_)            v = h[bn*INP_ + (k - FEAT - LAT_)];
        g_xin[idx] = tf32r(v);
    }
    if (idx < BN_*HZ_) {
        int bn = idx / HZ_, j = idx % HZ_;
        int k = kperm(j);
        float v = (k < LAT_) ? z[bn*LAT_ + k] : h[bn*INP_ + (k - LAT_)];
        g_hz[idx] = tf32r(v);
    }
    if (idx < BN_*FEAT) {
        int bn = idx / FEAT, f = idx % FEAT;
        int b = bn / Nn, n = bn % Nn;
        float xv = x[((b*2 + 1)*Nn + n)*FEAT + f];
        g_xc[idx] = xv;
        out[OFF_XT + idx] = xv;
    }
    if (idx < BN_*4) g_qc[idx] = qt[idx];
}

#define NW0  (NT_*HID_*XSTR)
#define NWIH (NT_*G3_*HZ_)
#define NWHH (NT_*G3_*HID_)
__global__ void kroundw(const float* __restrict__ W0, const float* __restrict__ Wih,
                        const float* __restrict__ Whh)
{
    int idx = blockIdx.x * blockDim.x + threadIdx.x;
    if (idx < NW0) {
        int row = idx / XSTR, j = idx % XSTR;
        int k = kperm(j);
        g_W0r[idx] = (k < IN0_) ? tf32r(W0[(size_t)row*IN0_ + k]) : 0.f;
    } else if (idx < NW0 + NWIH) {
        int jj = idx - NW0;
        int row = jj / HZ_, j = jj % HZ_;
        int k = kperm(j);
        g_Wihr[jj] = tf32r(Wih[(size_t)row * IN0_ + FEAT + k]);
    } else if (idx < NW0 + NWIH + NWHH) {
        int jj = idx - NW0 - NWIH;
        int row = jj / HID_, j = jj % HID_;
        int k = kperm(j);
        g_Whhr[jj] = tf32r(Whh[(size_t)row*HID_ + k]);
    }
}

__global__ void kbuildwqc(const float* __restrict__ Wq, const float* __restrict__ Wc,
                          const float* __restrict__ bq, const float* __restrict__ bc)
{
    int idx = blockIdx.x * blockDim.x + threadIdx.x;
    if (idx < NT_*256*HID_) {
        int t = idx / (256*HID_);
        int r = (idx / HID_) % 256;
        int j = idx % HID_;
        int k = kperm(j);
        float v = (r < 128) ? Wq[((size_t)t*128 + r)*HID_ + k]
                            : Wc[((size_t)t*128 + (r-128))*HID_ + k];
        g_Wqc[idx] = tf32r(v);
    }
    if (idx < Nn*256) {
        int n = idx / 256, c = idx % 256;
        g_bqc[idx] = (c < 128) ? bq[n*128 + c] : bc[n*128 + (c-128)];
    }
}

// ---------------- mma.sync tf32 GEMM: CTA 128x256, 256 thr, warp 64x64, BK=32, 3-stage ----------------
#define SSTG  (128*32 + 256*32)
#define NSTG3 3

__global__ void __launch_bounds__(256, 1) ktc(
    int asel, int lda, int wsel, int ldw,
    int G, int K,
    const float* biasg, int csel,
    const int* __restrict__ T, int ybase, int ystep)
{
    extern __shared__ float smx[];

    const float* A = (asel==0)?g_xin : (asel==1)?g_hrnd[0] : (asel==2)?g_hrnd[1]
                   : (asel==3)?g_y : g_hz;
    const float* W = (wsel==0)?g_W0r : (wsel==1)?g_Wihr : (wsel==2)?g_Whhr : g_Wqc;
    const float* bias = biasg ? biasg : g_bqc;
    float* C = (csel==0)?g_tmp0 : (csel==1)?g_base : (csel==2)?g_hr : g_pqc;

    int n  = blockIdx.z;
    int t  = T[n];
    int b0 = blockIdx.x * 128;
    int g0 = (ybase + blockIdx.y * ystep) * 256;
    int tid  = threadIdx.x;
    int wid  = tid >> 5, lane = tid & 31;
    int wm = wid >> 2, wn = wid & 3;
    int gq = lane >> 2, tg = lane & 3;

    const size_t strideA = (size_t)Nn * lda;
    const float* An = A + ((size_t)b0 * Nn + n) * lda;
    const float* Wt = W + ((size_t)t * G + g0) * ldw;
    uint32_t smb = smem_u32(smx);

    float acc[4][8][4];
    #pragma unroll
    for (int a = 0; a < 4; a++)
        #pragma unroll
        for (int b = 0; b < 8; b++)
            #pragma unroll
            for (int c = 0; c < 4; c++) acc[a][b][c] = 0.f;

    int ntiles = K >> 5;

    auto issue = [&](int kt, int buf) {
        int k0 = kt * 32;
        uint32_t sb = smb + buf * SSTG * 4;
        #pragma unroll
        for (int p = 0; p < 12; p++) {
            int id = p * 256 + tid;
            if (p < 4) {
                int row = id >> 3, c = id & 7;
                const float* src = An + (size_t)row * strideA + k0 + c*4;
                uint32_t dst = sb + (row*32 + ((c ^ ((row & 1) << 2)) << 2)) * 4;
                cpa16(dst, src);
            } else {
                int rid = id - 1024;
                int row = rid >> 3, c = rid & 7;
                const float* src = Wt + (size_t)row * ldw + k0 + c*4;
                uint32_t dst = sb + (4096 + row*32 + ((c ^ ((row & 1) << 2)) << 2)) * 4;
                cpa16(dst, src);
            }
        }
    };

    issue(0, 0); CP_COMMIT();
    issue(1, 1); CP_COMMIT();

    int ibuf = 2, cbuf = 0;
    for (int kt = 0; kt < ntiles; kt++) {
        if (kt + 1 < ntiles) CP_WAIT1(); else CP_WAIT0();
        __syncthreads();
        if (kt + 2 < ntiles) {
            issue(kt + 2, ibuf); CP_COMMIT();
            if (++ibuf == NSTG3) ibuf = 0;
        }

        const float* AsB = smx + cbuf * SSTG;
        const float* BsB = AsB + 4096;
        #pragma unroll
        for (int kh = 0; kh < 2; kh++) {
            float4 am[4], ah[4];
            #pragma unroll
            for (int mt = 0; mt < 4; mt++) {
                int row = wm*64 + mt*16 + gq;
                int ch = ((kh*4 + tg) ^ ((row & 1) << 2)) << 2;
                am[mt] = *(const float4*)(AsB + row*32 + ch);
                ah[mt] = *(const float4*)(AsB + (row + 8)*32 + ch);
            }
            #pragma unroll
            for (int nt = 0; nt < 8; nt++) {
                int col = wn*64 + nt*8 + gq;
                int ch = ((kh*4 + tg) ^ ((col & 1) << 2)) << 2;
                float4 bf = *(const float4*)(BsB + col*32 + ch);
                // interleave: xy-half for all mt, then zw-half for all mt
                // (separates dependent RAW pairs on the same accumulator by
                //  3 independent HMMAs; per-acc accumulation order unchanged)
                #pragma unroll
                for (int mt = 0; mt < 4; mt++) {
                    mma_tf32(acc[mt][nt],
                             __float_as_uint(am[mt].x), __float_as_uint(ah[mt].x),
                             __float_as_uint(am[mt].y), __float_as_uint(ah[mt].y),
                             __float_as_uint(bf.x), __float_as_uint(bf.y));
                }
                #pragma unroll
                for (int mt = 0; mt < 4; mt++) {
                    mma_tf32(acc[mt][nt],
                             __float_as_uint(am[mt].z), __float_as_uint(ah[mt].z),
                             __float_as_uint(am[mt].w), __float_as_uint(ah[mt].w),
                             __float_as_uint(bf.z), __float_as_uint(bf.w));
                }
            }
        }
        if (++cbuf == NSTG3) cbuf = 0;
    }

    const float* bp = bias + (size_t)n * G + g0;
    #pragma unroll
    for (int mt = 0; mt < 4; mt++) {
        int row = b0 + wm*64 + mt*16 + gq;
        float* C0 = C + ((size_t)row * Nn + n) * G + g0;
        float* C1 = C + ((size_t)(row + 8) * Nn + n) * G + g0;
        #pragma unroll
        for (int nt = 0; nt < 8; nt++) {
            int col = wn*64 + nt*8 + tg*2;
            float2 o0, o1;
            o0.x = acc[mt][nt][0] + bp[col];
            o0.y = acc[mt][nt][1] + bp[col + 1];
            o1.x = acc[mt][nt][2] + bp[col];
            o1.y = acc[mt][nt][3] + bp[col + 1];
            *(float2*)(C0 + col) = o0;
            *(float2*)(C1 + col) = o1;
        }
    }
}

__global__ void kmix_rnnh()
{
    int b = blockIdx.x, c0 = blockIdx.y * 64;
    __shared__ float sh[Nn][64];
    __shared__ float sG[Nn*Nn];
    int tid = threadIdx.x;
    for (int i = tid; i < Nn*Nn; i += 256) sG[i] = g_G0n[i];
    for (int i = tid; i < Nn*64; i += 256) {
        int m = i >> 6, c = i & 63;
        sh[m][c] = g_tmp0[((size_t)(b*Nn) + m) * HID_ + c0 + c];
    }
    __syncthreads();
    for (int i = tid; i < Nn*64; i += 256) {
        int n = i >> 6, c = i & 63;
        float s = 0.f;
        #pragma unroll
        for (int m = 0; m < Nn; m++) s += sG[n*Nn+m] * sh[m][c];
        size_t base = ((size_t)(b*Nn) + n) * HID_ + c0;
        g_h[0][base + c] = s;
        g_hrnd[0][base + kperm(c)] = tf32r(s);
    }
}

// ---------------- kgates v4 (n-blocked mix), channel-half split ----------------
#define KG_SSUM 0
#define KG_SX2  (2*Nn*64)
#define KG_SHH2 (3*Nn*64)
#define KG_SG   (4*Nn*64)
#define KG_SXW  ((KG_SG + Nn*Nn + 3) & ~3)
#define KG_SXC  (KG_SXW + 4*3*64*8)
#define KG_TOT  (KG_SXC + Nn*8)

__global__ void __launch_bounds__(256, 3) kgates(
    const float* __restrict__ Wih, const int* __restrict__ T, int cur, int c0base)
{
    extern __shared__ float sm[];
    __shared__ int sT[Nn];
    int b = blockIdx.x, c0 = c0base + blockIdx.y * 64;
    int tid = threadIdx.x;

    float* ssum = sm + KG_SSUM;
    float* sx2  = sm + KG_SX2;
    float* shh2 = sm + KG_SHH2;
    float* sG   = sm + KG_SG;
    float* sxw  = sm + KG_SXW;
    float* sxc  = sm + KG_SXC;

    if (tid < Nn) sT[tid] = T[tid];
    for (int i = tid; i < Nn*Nn; i += 256) sG[i] = g_Gn[i];
    for (int i = tid; i < Nn*8; i += 256) sxc[i] = g_xc[(size_t)b*Nn*FEAT + i];
    for (int i = tid; i < 4*3*64*2; i += 256) {
        int q4 = i & 1;
        int c  = (i >> 1) & 63;
        int s  = (i >> 7) % 3;
        int t  = i / (2*64*3);
        int g  = s*HID_ + c0 + c;
        float4 v = *(const float4*)(Wih + ((size_t)t * G3_ + g) * IN0_ + q4*4);
        *(float4*)(sxw + (((t*3 + s)*64 + c)*8) + q4*4) = v;
    }
    __syncthreads();

    for (int i = tid; i < 3*Nn*16; i += 256) {
        int s = i / (Nn*16);
        int rem = i % (Nn*16);
        int m = rem >> 4, q = rem & 15;
        int g = s*HID_ + c0 + q*4;
        size_t gi = ((size_t)(b*Nn) + m) * G3_ + g;
        float4 bs  = *(const float4*)(g_base + gi);
        float4 hr4 = *(const float4*)(g_hr + gi);
        const float* xc = sxc + m*8;
        int t = sT[m];
        const float* wxb = sxw + ((size_t)((t*3 + s)*64 + q*4))*8;
        float xr[4] = {bs.x, bs.y, bs.z, bs.w};
        #pragma unroll
        for (int j = 0; j < 4; j++) {
            const float* wr = wxb + j*8;
            #pragma unroll
            for (int k = 0; k < FEAT; k++) xr[j] += xc[k] * wr[k];
        }
        float hv[4] = {hr4.x, hr4.y, hr4.z, hr4.w};
        int off = m*64 + q*4;
        if (s < 2) {
            float* d = ssum + s*Nn*64 + off;
            #pragma unroll
            for (int j = 0; j < 4; j++) d[j] = xr[j] + hv[j];
        } else {
            #pragma unroll
            for (int j = 0; j < 4; j++) { sx2[off+j] = xr[j]; shh2[off+j] = hv[j]; }
        }
    }
    __syncthreads();

    {
        int c = tid & 63;
        int grp = tid >> 6;
        float a0[6], a1[6], a2[6], a3[6];
        #pragma unroll
        for (int j = 0; j < 6; j++) { a0[j]=0.f; a1[j]=0.f; a2[j]=0.f; a3[j]=0.f; }
        #pragma unroll
        for (int m = 0; m < Nn; m++) {
            float v0 = ssum[(0*Nn + m)*64 + c];
            float v1 = ssum[(1*Nn + m)*64 + c];
            float v2 = sx2[m*64 + c];
            float v3 = shh2[m*64 + c];
            #pragma unroll
            for (int j = 0; j < 6; j++) {
                int n = grp + 4*j;
                float gw = (n < Nn) ? sG[n*Nn + m] : 0.f;
                a0[j] += gw*v0; a1[j] += gw*v1; a2[j] += gw*v2; a3[j] += gw*v3;
            }
        }
        #pragma unroll
        for (int j = 0; j < 6; j++) {
            int n = grp + 4*j;
            if (n < Nn) {
                float r  = siga(a0[j]);
                float zg = siga(a1[j]);
                float nn = tanha(a2[j] + r*a3[j]);
                size_t base = ((size_t)(b*Nn) + n) * HID_ + c0;
                float hc = g_h[cur][base + c];
                float hnew = (1.f - zg)*nn + zg*hc;
                g_h[cur^1][base + c] = hnew;
                int cp = kperm(c);
                g_hrnd[cur^1][base + cp] = tf32r(hnew);
                g_y[base + cp] = tf32r(tanha(hnew));
            }
        }
    }
}

__global__ void __launch_bounds__(256) kheadmix(
    const float* __restrict__ W3, const float* __restrict__ b3,
    const float* __restrict__ W6, const float* __restrict__ b6,
    const int* __restrict__ T, float* __restrict__ out, int step)
{
    __shared__ float sq[Nn*OUTD];
    __shared__ float sc[Nn*OUTD];
    __shared__ float sy[Nn*OUTD];
    __shared__ float syc[Nn*OUTD];
    __shared__ float sGq[Nn*Nn], sGc[Nn*Nn];
    __shared__ int sT[Nn];

    int b = blockIdx.x;
    int tid = threadIdx.x;
    if (tid < Nn) sT[tid] = T[tid];
    for (int i = tid; i < Nn*Nn; i += 256) { sGq[i] = g_Gqn[i]; sGc[i] = g_Gcn[i]; }
    for (int i = tid; i < Nn*OUTD; i += 256) {
        int m = i >> 7, c = i & 127;
        sq[i] = g_pqc[((size_t)(b*Nn) + m) * 256 + c];
        sc[i] = g_pqc[((size_t)(b*Nn) + m) * 256 + 128 + c];
    }
    __syncthreads();
    for (int i = tid; i < Nn*OUTD; i += 256) {
        int n = i >> 7, c = i & 127;
        float s1 = 0.f, s2 = 0.f;
        #pragma unroll
        for (int m = 0; m < Nn; m++) {
            s1 += sGq[n*Nn+m] * sq[m*OUTD+c];
            s2 += sGc[n*Nn+m] * sc[m*OUTD+c];
        }
        sy[i]  = tanha(s1);
        syc[i] = tanha(s2);
    }
    __syncthreads();

    int wid = tid >> 5, lane = tid & 31;
    for (int n = wid; n < Nn; n += 8) {
        int t = sT[n];
        float val = 0.f;
        if (lane < 3) {
            const float* ys = sy + n*OUTD;
            const float* w  = W3 + ((size_t)t*3 + lane) * OUTD;
            #pragma unroll 8
            for (int k = 0; k < OUTD; k++) val += ys[k] * w[k];
            val += b3[n*3 + lane];
        } else if (lane < 9) {
            int a = lane - 3;
            const float* yc = syc + n*OUTD;
            const float* w  = W6 + ((size_t)t*6 + a) * OUTD;
            #pragma unroll 8
            for (int k = 0; k < OUTD; k++) val += yc[k] * w[k];
            val += b6[n*6 + a];
        }
        unsigned mask = 0xffffffffu;
        float v0 = __shfl_sync(mask, val, 0);
        float v1 = __shfl_sync(mask, val, 1);
        float v2 = __shfl_sync(mask, val, 2);
        float c0 = __shfl_sync(mask, val, 3);
        float c1 = __shfl_sync(mask, val, 4);
        float c2 = __shfl_sync(mask, val, 5);
        float c3 = __shfl_sync(mask, val, 6);
        float c4 = __shfl_sync(mask, val, 7);
        float c5 = __shfl_sync(mask, val, 8);
        if (lane == 0) {
            int bn = b*Nn + n;
            float theta = sqrtf(v0*v0 + v1*v1 + v2*v2);
            float w1 = cosf(0.5f * theta);
            float kk = (theta > 1e-8f) ? (sinf(0.5f*theta) / fmaxf(theta, 1e-8f)) : 0.5f;
            float dq0 = w1, dq1 = kk*v0, dq2 = kk*v1, dq3 = kk*v2;
            float* qc = g_qc + (size_t)bn * 4;
            float qw = qc[0], qx = qc[1], qy = qc[2], qz = qc[3];
            float nw = dq0*qw - (dq1*qx + dq2*qy + dq3*qz);
            float nx = dq0*qx + qw*dq1 + (dq2*qz - dq3*qy);
            float ny = dq0*qy + qw*dq2 + (dq3*qx - dq1*qz);
            float nz = dq0*qz + qw*dq3 + (dq1*qy - dq2*qx);
            qc[0]=nw; qc[1]=nx; qc[2]=ny; qc[3]=nz;
            float* xc = g_xc + (size_t)bn * FEAT;
            xc[0]=nw; xc[1]=nx; xc[2]=ny; xc[3]=nz;
            xc[4]=dq0; xc[5]=dq1; xc[6]=dq2; xc[7]=dq3;
            size_t od = ((size_t)b * PHs + step) * Nn + n;
            out[OFF_DQ  + od*4 + 0] = dq0; out[OFF_DQ + od*4 + 1] = dq1;
            out[OFF_DQ  + od*4 + 2] = dq2; out[OFF_DQ + od*4 + 3] = dq3;
            out[OFF_COV + od*6 + 0] = c0;  out[OFF_COV + od*6 + 1] = c1;
            out[OFF_COV + od*6 + 2] = c2;  out[OFF_COV + od*6 + 3] = c3;
            out[OFF_COV + od*6 + 4] = c4;  out[OFF_COV + od*6 + 5] = c5;
        }
    }
}

extern "C" void kernel_launch(void* const* d_in, const int* in_sizes, int n_in,
                              void* d_out, int out_size)
{
    const float* x    = (const float*)d_in[0];
    const float* h    = (const float*)d_in[1];
    const float* z    = (const float*)d_in[2];
    const float* q_t  = (const float*)d_in[3];
    const int*   T    = (const int*)  d_in[4];
    const float* W0   = (const float*)d_in[6];
    const float* b0p  = (const float*)d_in[7];
    const float* G0   = (const float*)d_in[8];
    const float* Wih  = (const float*)d_in[9];
    const float* Whh  = (const float*)d_in[10];
    const float* bih  = (const float*)d_in[11];
    const float* bhh  = (const float*)d_in[12];
    const float* Grnn = (const float*)d_in[13];
    const float* GA   = (const float*)d_in[14];
    const float* Wq   = (const float*)d_in[15];
    const float* bq   = (const float*)d_in[16];
    const float* Gq   = (const float*)d_in[17];
    const float* Wc   = (const float*)d_in[18];
    const float* bc   = (const float*)d_in[19];
    const float* Gc   = (const float*)d_in[20];
    const float* W3   = (const float*)d_in[21];
    const float* b3   = (const float*)d_in[22];
    const float* W6   = (const float*)d_in[23];
    const float* b6   = (const float*)d_in[24];
    float* out = (float*)d_out;

    const int SM_KTC = NSTG3 * SSTG * 4;
    const int SM_KG  = KG_TOT * 4;

    static cudaStream_t s_side = nullptr;
    static cudaEvent_t  s_evA = nullptr, s_e1a = nullptr, s_e1b = nullptr, s_evS = nullptr;
    static int attr_done = 0;
    if (!attr_done) {
        cudaFuncSetAttribute(ktc, cudaFuncAttributeMaxDynamicSharedMemorySize, SM_KTC);
        cudaFuncSetAttribute(kgates, cudaFuncAttributeMaxDynamicSharedMemorySize, SM_KG);
        cudaStreamCreateWithFlags(&s_side, cudaStreamNonBlocking);
        cudaEventCreateWithFlags(&s_evA, cudaEventDisableTiming);
        cudaEventCreateWithFlags(&s_e1a, cudaEventDisableTiming);
        cudaEventCreateWithFlags(&s_e1b, cudaEventDisableTiming);
        cudaEventCreateWithFlags(&s_evS, cudaEventDisableTiming);
        attr_done = 1;
    }
    cudaStream_t s0 = (cudaStream_t)0;

    knorms<<<1, 128>>>(G0, Grnn, GA, Gq, Gc);
    kprep<<<(BN_*XSTR + 255)/256, 256>>>(x, h, z, q_t, out);
    kroundw<<<(NW0 + NWIH + NWHH + 255)/256, 256>>>(W0, Wih, Whh);

    // launch #4 (ncu-captured): base = h_z(320) @ Wih_hz^T + bih
    ktc<<<dim3(2, 6, Nn), 256, SM_KTC>>>(4, HZ_, 1, HZ_, G3_, HZ_, bih, 1, T, 0, 1);

    kbuildwqc<<<(NT_*256*HID_ + 255)/256, 256>>>(Wq, Wc, bq, bc);

    // tmp0 = xin(352 padded) @ W0^T + b0
    ktc<<<dim3(2, 2, Nn), 256, SM_KTC>>>(0, XSTR, 0, XSTR, HID_, XSTR, b0p, 0, T, 0, 1);
    kmix_rnnh<<<dim3(B_, HID_/64), 256>>>();

    for (int t = 0; t < PHs; t++) {
        int cur = t & 1;
        // hrA: even N-blocks {0,2,4} (g slices needed by kgatesA: c0<256)
        if (t > 0) cudaStreamWaitEvent(s0, s_e1a, 0);
        ktc<<<dim3(2, 3, Nn), 256, SM_KTC, s0>>>(1 + cur, HID_, 2, HID_, G3_, HID_, bhh, 2, T, 0, 2);
        cudaEventRecord(s_evA, s0);
        // hrB: odd N-blocks {1,3,5}
        ktc<<<dim3(2, 3, Nn), 256, SM_KTC, s0>>>(1 + cur, HID_, 2, HID_, G3_, HID_, bhh, 2, T, 1, 2);
        // kgatesB (c0 >= 256)
        if (t > 0) cudaStreamWaitEvent(s0, s_evS, 0);
        kgates<<<dim3(B_, 4), 256, SM_KG, s0>>>(Wih, T, cur, 256);
        cudaEventRecord(s_e1b, s0);
        // kgatesA (c0 < 256) on side stream, overlapping hrB/kgatesB
        cudaStreamWaitEvent(s_side, s_evA, 0);
        kgates<<<dim3(B_, 4), 256, SM_KG, s_side>>>(Wih, T, cur, 0);
        cudaEventRecord(s_e1a, s_side);
        // output head: needs full g_y
        cudaStreamWaitEvent(s_side, s_e1b, 0);
        ktc<<<dim3(2, 1, Nn), 256, SM_KTC, s_side>>>(3, HID_, 3, HID_, 256, HID_, nullptr, 3, T, 0, 1);
        kheadmix<<<B_, 256, 0, s_side>>>(W3, b3, W6, b6, T, out, t);
        cudaEventRecord(s_evS, s_side);
    }
    cudaStreamWaitEvent(s0, s_evS, 0);
}